// round 9
// baseline (speedup 1.0000x reference)
#include <cuda_runtime.h>
#include <cstdint>

// Skinny GEMM via mma.sync tf32 with per-warp cp.async ring (depth 4).
// C[65536,40] = embs[65536,1024] @ W^T, W = [W_status(5); W_flight(30); pad]
// R9 change: CTA = 64 threads (2 warps), BM = 64, grid = 1024, launch_bounds
// (64,7) -> all 1024 CTAs co-resident across 148 SMs (6-7 per SM, no idle
// SMs, no 128-vs-148 wave quantization like the previous 512x128 config).
// Mainloop identical to R8 (proven correct): wait -> LDS-read -> prefetch ->
// commit per-warp ring, no barriers. B pad rows point at a safe row; their
// accumulators feed only unused output columns (35..39), so no masking.
// Raw fp32 bits as tf32 (RZ truncate), bias cancelled by corr in epilogue.

#define EMB    1024
#define NS     5
#define NF     30
#define NL     35
#define OUTC   63
#define BM     64
#define LSTR   41
#define NTH    64
#define NWARP  (NTH / 32)    // 2
#define NKB    (EMB / 16)    // 64 k16 blocks
#define DEPTH  4

// ring: [warp][stage][r*32+lane] float4 slots; per warp 4*4*32*16B = 8KB
#define STAGE_F4 128
#define WARP_F4  (DEPTH * STAGE_F4)

__device__ __forceinline__ void mma8(float* c, const uint32_t* a, const uint32_t* b) {
    asm volatile(
        "mma.sync.aligned.m16n8k8.row.col.f32.tf32.tf32.f32 "
        "{%0,%1,%2,%3}, {%4,%5,%6,%7}, {%8,%9}, {%0,%1,%2,%3};"
        : "+f"(c[0]), "+f"(c[1]), "+f"(c[2]), "+f"(c[3])
        : "r"(a[0]), "r"(a[1]), "r"(a[2]), "r"(a[3]), "r"(b[0]), "r"(b[1]));
}
__device__ __forceinline__ void cp16s(uint32_t dst, const float* src) {
    asm volatile("cp.async.cg.shared.global [%0], [%1], 16;" :: "r"(dst), "l"(src));
}
__device__ __forceinline__ void cp_commit() { asm volatile("cp.async.commit_group;"); }
template<int N> __device__ __forceinline__ void cp_wait() {
    asm volatile("cp.async.wait_group %0;" :: "n"(N));
}

__global__ __launch_bounds__(NTH, 7) void aux2_ring_kernel(
    const float* __restrict__ embs,
    const float* __restrict__ W_status,
    const float* __restrict__ b_status,
    const float* __restrict__ W_flight,
    const float* __restrict__ b_flight,
    float* __restrict__ out,
    int ntok)
{
    __shared__ __align__(16) char sraw[NWARP * WARP_F4 * 16];  // 16KB ring; Ls alias

    const int tid  = threadIdx.x;
    const int wid  = tid >> 5;
    const int lane = tid & 31;
    const int g    = lane >> 2;     // 0..7
    const int t    = lane & 3;      // 0..3
    const long tokw = (long)blockIdx.x * BM + wid * 32;

    // per-lane global A pointers: row tokw + r*8 + g, col 4t (advance 16/kb)
    const float* gptr[4];
#pragma unroll
    for (int r = 0; r < 4; ++r)
        gptr[r] = embs + (tokw + r * 8 + g) * EMB + 4 * t;

    uint32_t ringbase = (uint32_t)__cvta_generic_to_shared(sraw)
                      + (uint32_t)(wid * WARP_F4) * 16u;

    // B row pointers; rows >= 35 alias W_flight row 0 (safe address, outputs
    // from those rows land only in unused cols 35..39 -> no masking needed)
    const uint4* br[5];
#pragma unroll
    for (int nt = 0; nt < 5; ++nt) {
        int r = nt * 8 + g;
        const float* src = (r < NS) ? (W_status + r * EMB)
                                    : (W_flight + ((r < NL ? r : NS) - NS) * EMB);
        br[nt] = reinterpret_cast<const uint4*>(src + 4 * t);
    }

    float acc[2][5][4];
#pragma unroll
    for (int mt = 0; mt < 2; ++mt)
#pragma unroll
        for (int nt = 0; nt < 5; ++nt)
#pragma unroll
            for (int i = 0; i < 4; ++i) acc[mt][nt][i] = 0.0f;

    // ---- prologue: fill stages 0..3, one commit group per stage ----
#pragma unroll
    for (int s = 0; s < DEPTH; ++s) {
#pragma unroll
        for (int r = 0; r < 4; ++r)
            cp16s(ringbase + (uint32_t)(s * STAGE_F4 + r * 32 + lane) * 16u,
                  gptr[r] + s * 16);
        cp_commit();
    }

    // ---- mainloop: wait -> read -> prefetch -> commit; no barriers ----
#pragma unroll 4
    for (int kb = 0; kb < NKB; ++kb) {
        const int s = kb & (DEPTH - 1);

        cp_wait<DEPTH - 1>();   // stage kb's group complete -> slot s readable

        uint4 v[4];
#pragma unroll
        for (int r = 0; r < 4; ++r) {
            uint32_t sa = ringbase + (uint32_t)(s * STAGE_F4 + r * 32 + lane) * 16u;
            asm volatile("ld.shared.v4.u32 {%0,%1,%2,%3}, [%4];"
                         : "=r"(v[r].x), "=r"(v[r].y), "=r"(v[r].z), "=r"(v[r].w)
                         : "r"(sa));
        }

        // refill dead slot s with stage kb+DEPTH
        if (kb + DEPTH < NKB) {
#pragma unroll
            for (int r = 0; r < 4; ++r)
                cp16s(ringbase + (uint32_t)(s * STAGE_F4 + r * 32 + lane) * 16u,
                      gptr[r] + (kb + DEPTH) * 16);
        }
        cp_commit();

        uint4 b[5];
#pragma unroll
        for (int nt = 0; nt < 5; ++nt) b[nt] = br[nt][kb * 4];

        uint32_t af0[2][4] = {
            { v[0].x, v[1].x, v[0].y, v[1].y },
            { v[2].x, v[3].x, v[2].y, v[3].y } };
        uint32_t af1[2][4] = {
            { v[0].z, v[1].z, v[0].w, v[1].w },
            { v[2].z, v[3].z, v[2].w, v[3].w } };

#pragma unroll
        for (int nt = 0; nt < 5; ++nt) {
            uint32_t bf0[2] = { b[nt].x, b[nt].y };
            uint32_t bf1[2] = { b[nt].z, b[nt].w };
#pragma unroll
            for (int mt = 0; mt < 2; ++mt) {
                mma8(acc[mt][nt], af0[mt], bf0);
                mma8(acc[mt][nt], af1[mt], bf1);
            }
        }
    }

    cp_wait<0>();
    __syncthreads();          // ring dead; alias it as logits buffer

    // ---- epilogue: fragments -> logits smem ----
    float* Ls = reinterpret_cast<float*>(sraw);   // 64*41*4 = 10.5KB < 16KB
#pragma unroll
    for (int mt = 0; mt < 2; ++mt)
#pragma unroll
        for (int nt = 0; nt < 5; ++nt) {
            int r0 = wid * 32 + mt * 16 + g;
            int cc = nt * 8 + t * 2;
            if (cc < NL) {
                Ls[r0 * LSTR + cc]       = acc[mt][nt][0];
                Ls[(r0 + 8) * LSTR + cc] = acc[mt][nt][2];
            }
            if (cc + 1 < NL) {
                Ls[r0 * LSTR + cc + 1]       = acc[mt][nt][1];
                Ls[(r0 + 8) * LSTR + cc + 1] = acc[mt][nt][3];
            }
        }
    __syncthreads();

    // ---- per-thread dual softmax + store (thread tid = token) ----
    {
        const float corr = 1.000677f;   // tf32 RZ truncation bias compensation
        float sl[NS], fl[NF];
#pragma unroll
        for (int n = 0; n < NS; ++n) sl[n] = Ls[tid * LSTR + n] * corr + b_status[n];
#pragma unroll
        for (int n = 0; n < NF; ++n) fl[n] = Ls[tid * LSTR + NS + n] * corr + b_flight[n];

        float smax = sl[0];
#pragma unroll
        for (int n = 1; n < NS; ++n) smax = fmaxf(smax, sl[n]);
        float ssum = 0.f;
#pragma unroll
        for (int n = 0; n < NS; ++n) { sl[n] = __expf(sl[n] - smax); ssum += sl[n]; }
        float sinv = 1.f / ssum;
#pragma unroll
        for (int n = 0; n < NS; ++n) sl[n] *= sinv;

        float fm = fl[0];
#pragma unroll
        for (int n = 1; n < NF; ++n) fm = fmaxf(fm, fl[n]);
        float fsum = 0.f;
#pragma unroll
        for (int n = 0; n < NF; ++n) { fl[n] = __expf(fl[n] - fm); fsum += fl[n]; }
        float finv = 1.f / fsum;
#pragma unroll
        for (int n = 0; n < NF; ++n) fl[n] *= finv;

        const float book = sl[4], change = sl[3];
        long token = (long)blockIdx.x * BM + tid;
        if (token < ntok) {
            float* op = out + token * (long)OUTC;
            op[0] = sl[0];
            op[1] = sl[2];
            op[2] = sl[1];
#pragma unroll
            for (int j = 0; j < NF; ++j) {
                op[3 + j]  = book   * fl[j];
                op[33 + j] = change * fl[j];
            }
        }
    }
}

extern "C" void kernel_launch(void* const* d_in, const int* in_sizes, int n_in,
                              void* d_out, int out_size) {
    const float* embs     = (const float*)d_in[0];
    const float* W_status = (const float*)d_in[1];
    const float* b_status = (const float*)d_in[2];
    const float* W_flight = (const float*)d_in[3];
    const float* b_flight = (const float*)d_in[4];
    float* out = (float*)d_out;

    int ntok = in_sizes[0] / EMB;   // 65536
    int blocks = ntok / BM;         // 1024
    aux2_ring_kernel<<<blocks, NTH>>>(embs, W_status, b_status,
                                      W_flight, b_flight, out, ntok);
}

// round 10
// speedup vs baseline: 1.0501x; 1.0501x over previous
#include <cuda_runtime.h>
#include <cstdint>

// Skinny GEMM via mma.sync tf32 with per-warp cp.async ring.
// C[65536,40] = embs[65536,1024] @ W^T, W = [W_status(5); W_flight(30); pad]
// R10 vs R8: ring has 6 slots with 5 groups in flight, so the prefetch slot
// (kb+5)%6 never equals the read slot kb%6 -> prefetch is issued BEFORE the
// wait (hides issue under the stall, +25% in-flight bytes). B LDGs hoisted to
// the top of the iteration. Same proven fragment/K-permutation layout.
// Raw fp32 bits as tf32 (RZ truncate), bias cancelled by corr in epilogue.

#define EMB    1024
#define NS     5
#define NF     30
#define NL     35
#define OUTC   63
#define BM     128
#define LSTR   41
#define NTH    128
#define NWARP  4
#define NKB    (EMB / 16)    // 64 k16 blocks
#define SLOTS  6
#define INFLT  5             // groups in flight

// ring: [warp][slot][r*32+lane] float4; per warp 6*4*32*16B = 12KB; CTA 48KB
#define STAGE_F4 128
#define WARP_F4  (SLOTS * STAGE_F4)
#define SMEM_BYTES (NWARP * WARP_F4 * 16)   // 49152

__device__ __forceinline__ void mma8(float* c, const uint32_t* a, const uint32_t* b) {
    asm volatile(
        "mma.sync.aligned.m16n8k8.row.col.f32.tf32.tf32.f32 "
        "{%0,%1,%2,%3}, {%4,%5,%6,%7}, {%8,%9}, {%0,%1,%2,%3};"
        : "+f"(c[0]), "+f"(c[1]), "+f"(c[2]), "+f"(c[3])
        : "r"(a[0]), "r"(a[1]), "r"(a[2]), "r"(a[3]), "r"(b[0]), "r"(b[1]));
}
__device__ __forceinline__ void cp16s(uint32_t dst, const float* src) {
    asm volatile("cp.async.cg.shared.global [%0], [%1], 16;" :: "r"(dst), "l"(src));
}
__device__ __forceinline__ void cp_commit() { asm volatile("cp.async.commit_group;"); }
template<int N> __device__ __forceinline__ void cp_wait() {
    asm volatile("cp.async.wait_group %0;" :: "n"(N));
}

extern __shared__ __align__(16) char sraw[];

__global__ __launch_bounds__(NTH, 4) void aux2_ring6_kernel(
    const float* __restrict__ embs,
    const float* __restrict__ W_status,
    const float* __restrict__ b_status,
    const float* __restrict__ W_flight,
    const float* __restrict__ b_flight,
    float* __restrict__ out,
    int ntok)
{
    const int tid  = threadIdx.x;
    const int wid  = tid >> 5;
    const int lane = tid & 31;
    const int g    = lane >> 2;     // 0..7
    const int t    = lane & 3;      // 0..3
    const long tokw = (long)blockIdx.x * BM + wid * 32;

    // per-lane global A pointers: row tokw + r*8 + g, col 4t (advance 16/kb)
    const float* gptr[4];
#pragma unroll
    for (int r = 0; r < 4; ++r)
        gptr[r] = embs + (tokw + r * 8 + g) * EMB + 4 * t;

    uint32_t ringbase = (uint32_t)__cvta_generic_to_shared(sraw)
                      + (uint32_t)(wid * WARP_F4) * 16u;

    // B row pointers; rows >= 35 alias a safe row (outputs land in unused cols)
    const uint4* br[5];
#pragma unroll
    for (int nt = 0; nt < 5; ++nt) {
        int r = nt * 8 + g;
        const float* src = (r < NS) ? (W_status + r * EMB)
                                    : (W_flight + ((r < NL ? r : NS) - NS) * EMB);
        br[nt] = reinterpret_cast<const uint4*>(src + 4 * t);
    }

    float acc[2][5][4];
#pragma unroll
    for (int mt = 0; mt < 2; ++mt)
#pragma unroll
        for (int nt = 0; nt < 5; ++nt)
#pragma unroll
            for (int i = 0; i < 4; ++i) acc[mt][nt][i] = 0.0f;

    // ---- prologue: fill stages 0..4 (5 groups in flight) ----
#pragma unroll
    for (int s = 0; s < INFLT; ++s) {
#pragma unroll
        for (int r = 0; r < 4; ++r)
            cp16s(ringbase + (uint32_t)(s * STAGE_F4 + r * 32 + lane) * 16u,
                  gptr[r] + s * 16);
        cp_commit();
    }

    // ---- mainloop: B-loads -> prefetch -> commit -> wait -> LDS -> MMA ----
    int sr = 0;                   // kb % 6 (read slot)
    int sp = INFLT;               // (kb+5) % 6 (prefetch slot)
#pragma unroll 2
    for (int kb = 0; kb < NKB; ++kb) {
        // B first: independent of the ring, latency overlaps everything below
        uint4 b[5];
#pragma unroll
        for (int nt = 0; nt < 5; ++nt) b[nt] = br[nt][kb * 4];

        // prefetch stage kb+INFLT into slot sp (!= sr), BEFORE the wait
        if (kb + INFLT < NKB) {
#pragma unroll
            for (int r = 0; r < 4; ++r)
                cp16s(ringbase + (uint32_t)(sp * STAGE_F4 + r * 32 + lane) * 16u,
                      gptr[r] + (kb + INFLT) * 16);
        }
        cp_commit();              // unconditional: uniform group accounting

        cp_wait<INFLT>();         // 6 pending -> oldest (stage kb) complete

        uint4 v[4];
#pragma unroll
        for (int r = 0; r < 4; ++r) {
            uint32_t sa = ringbase + (uint32_t)(sr * STAGE_F4 + r * 32 + lane) * 16u;
            asm volatile("ld.shared.v4.u32 {%0,%1,%2,%3}, [%4];"
                         : "=r"(v[r].x), "=r"(v[r].y), "=r"(v[r].z), "=r"(v[r].w)
                         : "r"(sa));
        }

        uint32_t af0[2][4] = {
            { v[0].x, v[1].x, v[0].y, v[1].y },
            { v[2].x, v[3].x, v[2].y, v[3].y } };
        uint32_t af1[2][4] = {
            { v[0].z, v[1].z, v[0].w, v[1].w },
            { v[2].z, v[3].z, v[2].w, v[3].w } };

#pragma unroll
        for (int nt = 0; nt < 5; ++nt) {
            uint32_t bf0[2] = { b[nt].x, b[nt].y };
            uint32_t bf1[2] = { b[nt].z, b[nt].w };
#pragma unroll
            for (int mt = 0; mt < 2; ++mt) {
                mma8(acc[mt][nt], af0[mt], bf0);
                mma8(acc[mt][nt], af1[mt], bf1);
            }
        }

        sr = (sr == SLOTS - 1) ? 0 : sr + 1;
        sp = (sp == SLOTS - 1) ? 0 : sp + 1;
    }

    cp_wait<0>();
    __syncthreads();          // ring dead; alias as logits buffer

    // ---- epilogue: fragments -> logits smem ----
    float* Ls = reinterpret_cast<float*>(sraw);   // 128*41*4 = 21KB < 48KB
#pragma unroll
    for (int mt = 0; mt < 2; ++mt)
#pragma unroll
        for (int nt = 0; nt < 5; ++nt) {
            int r0 = wid * 32 + mt * 16 + g;
            int cc = nt * 8 + t * 2;
            if (cc < NL) {
                Ls[r0 * LSTR + cc]       = acc[mt][nt][0];
                Ls[(r0 + 8) * LSTR + cc] = acc[mt][nt][2];
            }
            if (cc + 1 < NL) {
                Ls[r0 * LSTR + cc + 1]       = acc[mt][nt][1];
                Ls[(r0 + 8) * LSTR + cc + 1] = acc[mt][nt][3];
            }
        }
    __syncthreads();

    // ---- per-thread dual softmax + store (thread tid = token) ----
    {
        const float corr = 1.000677f;   // tf32 RZ truncation bias compensation
        float sl[NS], fl[NF];
#pragma unroll
        for (int n = 0; n < NS; ++n) sl[n] = Ls[tid * LSTR + n] * corr + b_status[n];
#pragma unroll
        for (int n = 0; n < NF; ++n) fl[n] = Ls[tid * LSTR + NS + n] * corr + b_flight[n];

        float smax = sl[0];
#pragma unroll
        for (int n = 1; n < NS; ++n) smax = fmaxf(smax, sl[n]);
        float ssum = 0.f;
#pragma unroll
        for (int n = 0; n < NS; ++n) { sl[n] = __expf(sl[n] - smax); ssum += sl[n]; }
        float sinv = 1.f / ssum;
#pragma unroll
        for (int n = 0; n < NS; ++n) sl[n] *= sinv;

        float fm = fl[0];
#pragma unroll
        for (int n = 1; n < NF; ++n) fm = fmaxf(fm, fl[n]);
        float fsum = 0.f;
#pragma unroll
        for (int n = 0; n < NF; ++n) { fl[n] = __expf(fl[n] - fm); fsum += fl[n]; }
        float finv = 1.f / fsum;
#pragma unroll
        for (int n = 0; n < NF; ++n) fl[n] *= finv;

        const float book = sl[4], change = sl[3];
        long token = (long)blockIdx.x * BM + tid;
        if (token < ntok) {
            float* op = out + token * (long)OUTC;
            op[0] = sl[0];
            op[1] = sl[2];
            op[2] = sl[1];
#pragma unroll
            for (int j = 0; j < NF; ++j) {
                op[3 + j]  = book   * fl[j];
                op[33 + j] = change * fl[j];
            }
        }
    }
}

extern "C" void kernel_launch(void* const* d_in, const int* in_sizes, int n_in,
                              void* d_out, int out_size) {
    const float* embs     = (const float*)d_in[0];
    const float* W_status = (const float*)d_in[1];
    const float* b_status = (const float*)d_in[2];
    const float* W_flight = (const float*)d_in[3];
    const float* b_flight = (const float*)d_in[4];
    float* out = (float*)d_out;

    cudaFuncSetAttribute(aux2_ring6_kernel,
                         cudaFuncAttributeMaxDynamicSharedMemorySize, SMEM_BYTES);

    int ntok = in_sizes[0] / EMB;   // 65536
    int blocks = ntok / BM;         // 512
    aux2_ring6_kernel<<<blocks, NTH, SMEM_BYTES>>>(embs, W_status, b_status,
                                                   W_flight, b_flight, out, ntok);
}